// round 4
// baseline (speedup 1.0000x reference)
#include <cuda_runtime.h>
#include <cstdint>
#include <math.h>

#define NMAX 100000
#define MA   1024
#define KNN  10

__device__ float g_hidden[(size_t)NMAX * 128];
__device__ float g_S[(size_t)NMAX * MA];
__device__ int   g_tkidx[(size_t)NMAX * KNN];
__device__ float g_tkw[(size_t)NMAX * KNN];
__device__ float g_t1b[(size_t)NMAX * 32];
__device__ float g_t2a[MA * 128];
__device__ float g_g1[MA * 32];
__device__ float g_t2b[MA * 32];
__device__ float g_dinv[MA];
__device__ int   g_cnt[MA];
__device__ int   g_offs[MA + 1];
__device__ int   g_cur[MA];
__device__ int   g_brow[(size_t)NMAX * KNN];
__device__ float g_bw[(size_t)NMAX * KNN];
__device__ float g_anchorT[128 * MA];

__device__ __forceinline__ float lrelu(float x) { return x > 0.f ? x : 0.01f * x; }
__device__ __forceinline__ uint32_t rotl32(uint32_t x, int r) { return (x << r) | (x >> (32 - r)); }
__device__ __forceinline__ void tf4(uint32_t& x0, uint32_t& x1, int a, int b, int c, int d) {
    x0 += x1; x1 = rotl32(x1, a); x1 ^= x0;
    x0 += x1; x1 = rotl32(x1, b); x1 ^= x0;
    x0 += x1; x1 = rotl32(x1, c); x1 ^= x0;
    x0 += x1; x1 = rotl32(x1, d); x1 ^= x0;
}
__device__ __forceinline__ float erfinv_xla(float x) {
    float w = -log1pf(-x * x), p;
    if (w < 5.0f) {
        w -= 2.5f;
        p = 2.81022636e-08f;
        p = fmaf(p, w, 3.43273939e-07f);  p = fmaf(p, w, -3.5233877e-06f);
        p = fmaf(p, w, -4.39150654e-06f); p = fmaf(p, w, 0.00021858087f);
        p = fmaf(p, w, -0.00125372503f);  p = fmaf(p, w, -0.00417768164f);
        p = fmaf(p, w, 0.246640727f);     p = fmaf(p, w, 1.50140941f);
    } else {
        w = sqrtf(w) - 3.0f;
        p = -0.000200214257f;
        p = fmaf(p, w, 0.000100950558f);  p = fmaf(p, w, 0.00134934322f);
        p = fmaf(p, w, -0.00367342844f);  p = fmaf(p, w, 0.00573950773f);
        p = fmaf(p, w, -0.0076224613f);   p = fmaf(p, w, 0.00943887047f);
        p = fmaf(p, w, 1.00167406f);      p = fmaf(p, w, 2.83297682f);
    }
    return p * x;
}
// JAX partitionable threefry path (default in modern JAX):
// per element i: counter pair (hi=0, lo=i), bits = x0_out ^ x1_out
__device__ __forceinline__ float jax_normal42(uint32_t i) {
    const uint32_t ks0 = 0u, ks1 = 42u, ks2 = 0x1BD11BDAu ^ ks0 ^ ks1;
    uint32_t x0 = 0u + ks0, x1 = i + ks1;
    tf4(x0, x1, 13, 15, 26, 6);  x0 += ks1; x1 += ks2 + 1u;
    tf4(x0, x1, 17, 29, 16, 24); x0 += ks2; x1 += ks0 + 2u;
    tf4(x0, x1, 13, 15, 26, 6);  x0 += ks0; x1 += ks1 + 3u;
    tf4(x0, x1, 17, 29, 16, 24); x0 += ks1; x1 += ks2 + 4u;
    tf4(x0, x1, 13, 15, 26, 6);  x0 += ks2; x1 += ks0 + 5u;
    const uint32_t bits = x0 ^ x1;
    float f = __uint_as_float((bits >> 9) | 0x3f800000u) - 1.0f;
    const float lo = -0.99999994f;
    float u = fmaxf(fmaf(f, 1.0f - lo, lo), lo);
    return 1.41421356f * erfinv_xla(u);
}

// C[M x Nc] tiles of 128x128, BK=8, 8x8 per thread.
// EPI 0: plain store. 1: bias+lrelu (grid.y==1). 2: bias+lrelu+row-l2norm (Nc==128).
template<int KD, int EPI>
__global__ __launch_bounds__(256)
void gemm128(const float* __restrict__ A, const float* __restrict__ B,
             const float* __restrict__ bias, float* __restrict__ C,
             int M, int ldb, int ldc)
{
    __shared__ float As[8 * 132];
    __shared__ float Bs[8 * 128];
    const int tid = threadIdx.x, ty = tid >> 4, tx = tid & 15;
    const int rowBase = blockIdx.x * 128, colBase = blockIdx.y * 128;
    const int la_row = tid >> 1, la_kq = (tid & 1) * 4;
    const int lb_k = tid >> 5, lb_c = (tid & 31) * 4;
    float acc[8][8];
#pragma unroll
    for (int i = 0; i < 8; i++)
#pragma unroll
        for (int j = 0; j < 8; j++) acc[i][j] = 0.f;
    for (int k0 = 0; k0 < KD; k0 += 8) {
        float4 av = make_float4(0.f, 0.f, 0.f, 0.f);
        const int gr = rowBase + la_row;
        if (gr < M) av = *(const float4*)(A + (size_t)gr * KD + k0 + la_kq);
        const float4 bv = *(const float4*)(B + (size_t)(k0 + lb_k) * ldb + colBase + lb_c);
        __syncthreads();
        As[(la_kq + 0) * 132 + la_row] = av.x;
        As[(la_kq + 1) * 132 + la_row] = av.y;
        As[(la_kq + 2) * 132 + la_row] = av.z;
        As[(la_kq + 3) * 132 + la_row] = av.w;
        *(float4*)(Bs + lb_k * 128 + lb_c) = bv;
        __syncthreads();
#pragma unroll
        for (int kk = 0; kk < 8; kk++) {
            float4 a0 = *(const float4*)(As + kk * 132 + ty * 8);
            float4 a1 = *(const float4*)(As + kk * 132 + ty * 8 + 4);
            float4 b0 = *(const float4*)(Bs + kk * 128 + tx * 8);
            float4 b1 = *(const float4*)(Bs + kk * 128 + tx * 8 + 4);
            float a[8] = {a0.x, a0.y, a0.z, a0.w, a1.x, a1.y, a1.z, a1.w};
            float b[8] = {b0.x, b0.y, b0.z, b0.w, b1.x, b1.y, b1.z, b1.w};
#pragma unroll
            for (int i = 0; i < 8; i++)
#pragma unroll
                for (int j = 0; j < 8; j++) acc[i][j] = fmaf(a[i], b[j], acc[i][j]);
        }
    }
    if (EPI == 0) {
#pragma unroll
        for (int i = 0; i < 8; i++) {
            const int row = rowBase + ty * 8 + i;
            if (row < M) {
                *(float4*)(C + (size_t)row * ldc + colBase + tx * 8) =
                    make_float4(acc[i][0], acc[i][1], acc[i][2], acc[i][3]);
                *(float4*)(C + (size_t)row * ldc + colBase + tx * 8 + 4) =
                    make_float4(acc[i][4], acc[i][5], acc[i][6], acc[i][7]);
            }
        }
    } else if (EPI == 1) {
        float bv[8];
#pragma unroll
        for (int j = 0; j < 8; j++) bv[j] = bias[tx * 8 + j];
#pragma unroll
        for (int i = 0; i < 8; i++) {
            const int row = rowBase + ty * 8 + i;
            if (row < M) {
                float v[8];
#pragma unroll
                for (int j = 0; j < 8; j++) v[j] = lrelu(acc[i][j] + bv[j]);
                *(float4*)(C + (size_t)row * ldc + tx * 8)     = make_float4(v[0], v[1], v[2], v[3]);
                *(float4*)(C + (size_t)row * ldc + tx * 8 + 4) = make_float4(v[4], v[5], v[6], v[7]);
            }
        }
    } else {
        __shared__ float sred[128 * 16];
        __shared__ float snorm[128];
        float bv[8];
#pragma unroll
        for (int j = 0; j < 8; j++) bv[j] = bias[tx * 8 + j];
        float vals[8][8];
#pragma unroll
        for (int i = 0; i < 8; i++) {
            float ps = 0.f;
#pragma unroll
            for (int j = 0; j < 8; j++) {
                float v = lrelu(acc[i][j] + bv[j]);
                vals[i][j] = v;
                ps = fmaf(v, v, ps);
            }
            sred[(ty * 8 + i) * 16 + tx] = ps;
        }
        __syncthreads();
        if (tid < 128) {
            float s = 0.f;
#pragma unroll
            for (int x = 0; x < 16; x++) s += sred[tid * 16 + x];
            snorm[tid] = 1.f / fmaxf(sqrtf(s), 1e-12f);
        }
        __syncthreads();
#pragma unroll
        for (int i = 0; i < 8; i++) {
            const int row = rowBase + ty * 8 + i;
            if (row < M) {
                const float inv = snorm[ty * 8 + i];
                float v[8];
#pragma unroll
                for (int j = 0; j < 8; j++) v[j] = vals[i][j] * inv;
                *(float4*)(C + (size_t)row * ldc + tx * 8)     = make_float4(v[0], v[1], v[2], v[3]);
                *(float4*)(C + (size_t)row * ldc + tx * 8 + 4) = make_float4(v[4], v[5], v[6], v[7]);
            }
        }
    }
}

__global__ void fuse_kernel(const float* __restrict__ Z0, const float* __restrict__ Z1,
                            float* __restrict__ FZ, int n)
{
    const int row = (blockIdx.x * blockDim.x + threadIdx.x) >> 5;
    const int lane = threadIdx.x & 31;
    if (row >= n) return;
    const float* z0 = Z0 + (size_t)row * 128;
    const float* z1 = Z1 + (size_t)row * 128;
    float v[4]; float ss = 0.f;
#pragma unroll
    for (int q = 0; q < 4; q++) {
        v[q] = (z0[lane + 32 * q] + z1[lane + 32 * q]) * 0.5f;
        ss = fmaf(v[q], v[q], ss);
    }
#pragma unroll
    for (int off = 16; off; off >>= 1) ss += __shfl_xor_sync(0xffffffffu, ss, off);
    const float inv = 1.f / fmaxf(sqrtf(ss), 1e-12f);
    float* o = FZ + (size_t)row * 128;
#pragma unroll
    for (int q = 0; q < 4; q++) o[lane + 32 * q] = v[q] * inv;
}

__global__ void anchor_kernel(const float* __restrict__ FZ,
                              const float* __restrict__ mu_w, const float* __restrict__ mu_b,
                              const float* __restrict__ zita_w, const float* __restrict__ zita_b,
                              const float* __restrict__ prelu_w, float* __restrict__ AN)
{
    __shared__ float a0[128];
    __shared__ float red[128];
    __shared__ float s_inv;
    const int r = blockIdx.x, t = threadIdx.x;
    a0[t] = FZ[(size_t)r * 128 + t];
    __syncthreads();
    float mu = 0.f, zi = 0.f;
#pragma unroll 4
    for (int k = 0; k < 128; k++) {
        const float a = a0[k];
        mu = fmaf(a, mu_w[k * 128 + t], mu);
        zi = fmaf(a, zita_w[k * 128 + t], zi);
    }
    mu += mu_b[t]; zi += zita_b[t];
    mu = (mu >= 0.f) ? mu : prelu_w[t] * mu;
    zi = fmaxf(zi, 0.f);
    const float val = a0[t] + mu + zi * jax_normal42((uint32_t)(r * 128 + t));
    red[t] = val * val;
    __syncthreads();
    for (int s = 64; s; s >>= 1) { if (t < s) red[t] += red[t + s]; __syncthreads(); }
    if (t == 0) s_inv = 1.f / fmaxf(sqrtf(red[0]), 1e-12f);
    __syncthreads();
    AN[(size_t)r * 128 + t] = val * s_inv;
}

__global__ void anchorT_kernel(const float* __restrict__ AN) {
    const int i = blockIdx.x * blockDim.x + threadIdx.x;
    if (i < 128 * MA) g_anchorT[i] = AN[(size_t)(i & 1023) * 128 + (i >> 10)];
}

__global__ void zero_kernel(float4* __restrict__ p, size_t n4) {
    const size_t i = (size_t)blockIdx.x * blockDim.x + threadIdx.x;
    if (i < n4) p[i] = make_float4(0.f, 0.f, 0.f, 0.f);
}

__global__ __launch_bounds__(256)
void topk_kernel(const float* __restrict__ S, int n,
                 int* __restrict__ tidx, float* __restrict__ tw, float* __restrict__ Aout)
{
    const int row = (blockIdx.x * 256 + threadIdx.x) >> 5;
    const int lane = threadIdx.x & 31, wl = threadIdx.x >> 5;
    __shared__ float sv[8][KNN];
    __shared__ int   sj[8][KNN];
    if (row >= n) return;
    const float* srow = S + (size_t)row * MA;
    float v[32];
#pragma unroll
    for (int t = 0; t < 32; t++) v[t] = srow[lane + t * 32];
    unsigned used = 0;
    for (int it = 0; it < KNN; it++) {
        float best = -2.0f; int bj = 0x7fffffff;
#pragma unroll
        for (int t = 0; t < 32; t++)
            if (!((used >> t) & 1u) && v[t] > best) { best = v[t]; bj = lane + t * 32; }
#pragma unroll
        for (int off = 16; off; off >>= 1) {
            float ov = __shfl_down_sync(0xffffffffu, best, off);
            int   oj = __shfl_down_sync(0xffffffffu, bj, off);
            if (ov > best || (ov == best && oj < bj)) { best = ov; bj = oj; }
        }
        best = __shfl_sync(0xffffffffu, best, 0);
        bj   = __shfl_sync(0xffffffffu, bj, 0);
        if ((bj & 31) == lane) used |= 1u << (bj >> 5);
        if (lane == 0) { sv[wl][it] = best; sj[wl][it] = bj; }
    }
    __syncwarp();
    const float m = sv[wl][0];
    float e = (lane < KNN) ? expf(sv[wl][lane] - m) : 0.f;
    float s = e;
#pragma unroll
    for (int off = 16; off; off >>= 1) s += __shfl_xor_sync(0xffffffffu, s, off);
    if (lane < KNN) {
        const float wgt = e / s;
        const int j = sj[wl][lane];
        tidx[(size_t)row * KNN + lane] = j;
        tw[(size_t)row * KNN + lane]   = wgt;
        Aout[(size_t)row * MA + j]     = wgt;
    }
}

__global__ void reset_kernel() {
    const int i = blockIdx.x * blockDim.x + threadIdx.x;
    if (i < MA) g_cnt[i] = 0;
}
__global__ void count_kernel(const int* __restrict__ tidx, int nn) {
    const int i = blockIdx.x * blockDim.x + threadIdx.x;
    if (i < nn) atomicAdd(&g_cnt[tidx[i]], 1);
}
__global__ void scan_kernel() {
    __shared__ int s[MA];
    const int t = threadIdx.x;
    const int c = g_cnt[t];
    s[t] = c;
    __syncthreads();
    for (int d = 1; d < MA; d <<= 1) {
        int v = (t >= d) ? s[t - d] : 0;
        __syncthreads();
        s[t] += v;
        __syncthreads();
    }
    g_offs[t] = s[t] - c;
    g_cur[t]  = s[t] - c;
    if (t == MA - 1) g_offs[MA] = s[t];
}
__global__ void fill_kernel(const int* __restrict__ tidx, const float* __restrict__ tw, int nn) {
    const int i = blockIdx.x * blockDim.x + threadIdx.x;
    if (i < nn) {
        const int p = atomicAdd(&g_cur[tidx[i]], 1);
        g_brow[p] = i / KNN;
        g_bw[p]   = tw[i];
    }
}

__global__ void spmm_row128(const int* __restrict__ tidx, const float* __restrict__ tw,
                            const float* __restrict__ F, float* __restrict__ T1, int n)
{
    const int row = (blockIdx.x * blockDim.x + threadIdx.x) >> 5;
    const int lane = threadIdx.x & 31;
    if (row >= n) return;
    int myj = 0; float myw = 0.f;
    if (lane < KNN) { myj = tidx[(size_t)row * KNN + lane]; myw = tw[(size_t)row * KNN + lane]; }
    float a0 = 0.f, a1 = 0.f, a2 = 0.f, a3 = 0.f;
#pragma unroll
    for (int k = 0; k < KNN; k++) {
        const int   j = __shfl_sync(0xffffffffu, myj, k);
        const float w = __shfl_sync(0xffffffffu, myw, k);
        const float* fr = F + (size_t)j * 128;
        a0 = fmaf(w, fr[lane], a0);
        a1 = fmaf(w, fr[lane + 32], a1);
        a2 = fmaf(w, fr[lane + 64], a2);
        a3 = fmaf(w, fr[lane + 96], a3);
    }
    float* o = T1 + (size_t)row * 128;
    o[lane] = a0; o[lane + 32] = a1; o[lane + 64] = a2; o[lane + 96] = a3;
}

__global__ void spmm_row32(const int* __restrict__ tidx, const float* __restrict__ tw,
                           const float* __restrict__ F, float* __restrict__ T1, int n)
{
    const int row = (blockIdx.x * blockDim.x + threadIdx.x) >> 5;
    const int lane = threadIdx.x & 31;
    if (row >= n) return;
    int myj = 0; float myw = 0.f;
    if (lane < KNN) { myj = tidx[(size_t)row * KNN + lane]; myw = tw[(size_t)row * KNN + lane]; }
    float a0 = 0.f;
#pragma unroll
    for (int k = 0; k < KNN; k++) {
        const int   j = __shfl_sync(0xffffffffu, myj, k);
        const float w = __shfl_sync(0xffffffffu, myw, k);
        a0 = fmaf(w, F[(size_t)j * 32 + lane], a0);
    }
    T1[(size_t)row * 32 + lane] = a0;
}

__global__ __launch_bounds__(128)
void conv_t2_128(const float* __restrict__ T1, float* __restrict__ T2)
{
    const int j = blockIdx.x;
    const int lane = threadIdx.x & 31, w = threadIdx.x >> 5;
    const int s = g_offs[j], e = g_offs[j + 1];
    float a0 = 0.f, a1 = 0.f, a2 = 0.f, a3 = 0.f, sw = 0.f;
    for (int t = s + w; t < e; t += 4) {
        const int row = g_brow[t];
        const float ww = g_bw[t];
        sw += ww;
        const float* tr = T1 + (size_t)row * 128;
        a0 = fmaf(ww, tr[lane], a0);
        a1 = fmaf(ww, tr[lane + 32], a1);
        a2 = fmaf(ww, tr[lane + 64], a2);
        a3 = fmaf(ww, tr[lane + 96], a3);
    }
    __shared__ float sacc[4][128];
    __shared__ float ssw[4];
    sacc[w][lane] = a0; sacc[w][lane + 32] = a1; sacc[w][lane + 64] = a2; sacc[w][lane + 96] = a3;
    if (lane == 0) ssw[w] = sw;
    __syncthreads();
    const int c = threadIdx.x;
    const float tot = sacc[0][c] + sacc[1][c] + sacc[2][c] + sacc[3][c];
    const float d = ssw[0] + ssw[1] + ssw[2] + ssw[3];
    const float di = (d > 0.f) ? 1.f / d : 0.f;
    T2[(size_t)j * 128 + c] = tot * di;
    if (c == 0) g_dinv[j] = di;
}

__global__ __launch_bounds__(128)
void conv_t2_32(const float* __restrict__ T1b, float* __restrict__ T2b)
{
    const int j = blockIdx.x;
    const int lane = threadIdx.x & 31, w = threadIdx.x >> 5;
    const int s = g_offs[j], e = g_offs[j + 1];
    float a0 = 0.f;
    for (int t = s + w; t < e; t += 4)
        a0 = fmaf(g_bw[t], T1b[(size_t)g_brow[t] * 32 + lane], a0);
    __shared__ float sacc[4][32];
    sacc[w][lane] = a0;
    __syncthreads();
    if (threadIdx.x < 32)
        T2b[(size_t)j * 32 + lane] =
            (sacc[0][lane] + sacc[1][lane] + sacc[2][lane] + sacc[3][lane]) * g_dinv[j];
}

__global__ void g1_kernel(const float* __restrict__ T2a, const float* __restrict__ w1,
                          float* __restrict__ G1)
{
    const int j = blockIdx.x, t = threadIdx.x;
    float acc = 0.f;
#pragma unroll 4
    for (int k = 0; k < 128; k++) acc = fmaf(T2a[(size_t)j * 128 + k], w1[k * 32 + t], acc);
    G1[(size_t)j * 32 + t] = lrelu(acc);
}

__global__ void q_kernel(const float* __restrict__ T2b, const float* __restrict__ w2,
                         float* __restrict__ Q)
{
    const int j = (blockIdx.x * blockDim.x + threadIdx.x) >> 5;
    const int lane = threadIdx.x & 31;
    if (j >= MA) return;
    float acc = 0.f;
    if (lane < KNN) {
#pragma unroll
        for (int k = 0; k < 32; k++) acc = fmaf(T2b[(size_t)j * 32 + k], w2[k * 10 + lane], acc);
    }
    float m = (lane < KNN) ? acc : -1e30f;
#pragma unroll
    for (int off = 16; off; off >>= 1) m = fmaxf(m, __shfl_xor_sync(0xffffffffu, m, off));
    float e = (lane < KNN) ? expf(acc - m) : 0.f;
    float s = e;
#pragma unroll
    for (int off = 16; off; off >>= 1) s += __shfl_xor_sync(0xffffffffu, s, off);
    if (lane < KNN) Q[(size_t)j * 10 + lane] = e / s;
}

extern "C" void kernel_launch(void* const* d_in, const int* in_sizes, int n_in,
                              void* d_out, int out_size)
{
    const float* X[2]    = { (const float*)d_in[0], (const float*)d_in[1] };
    const float* enc1_w  = (const float*)d_in[2];
    const float* enc1_b  = (const float*)d_in[3];
    const float* enc2_w  = (const float*)d_in[4];
    const float* enc2_b  = (const float*)d_in[5];
    const float* mu_w    = (const float*)d_in[6];
    const float* mu_b    = (const float*)d_in[7];
    const float* zita_w  = (const float*)d_in[8];
    const float* zita_b  = (const float*)d_in[9];
    const float* prelu_w = (const float*)d_in[10];
    const float* agcn1_w = (const float*)d_in[11];
    const float* agcn2_w = (const float*)d_in[12];

    const int n = in_sizes[0] / 256;   // 100000
    float* out = (float*)d_out;
    float* Z[2];
    Z[0] = out;
    Z[1] = out + (size_t)n * 128;
    float* ANC = out + (size_t)2 * n * 128;
    float* FZ  = ANC + (size_t)MA * 128;
    float* Adn[2];
    Adn[0] = FZ + (size_t)n * 128;
    Adn[1] = Adn[0] + (size_t)n * MA;
    float* Q[2];
    Q[0] = Adn[1] + (size_t)n * MA;
    Q[1] = Q[0] + (size_t)MA * 10;

    float *g_hidden_p, *g_S_p, *g_t1b_p, *g_t2a_p, *g_g1_p, *g_t2b_p;
    int *g_tkidx_p; float *g_tkw_p;
    cudaGetSymbolAddress((void**)&g_hidden_p, g_hidden);
    cudaGetSymbolAddress((void**)&g_S_p, g_S);
    cudaGetSymbolAddress((void**)&g_tkidx_p, g_tkidx);
    cudaGetSymbolAddress((void**)&g_tkw_p, g_tkw);
    cudaGetSymbolAddress((void**)&g_t1b_p, g_t1b);
    cudaGetSymbolAddress((void**)&g_t2a_p, g_t2a);
    cudaGetSymbolAddress((void**)&g_g1_p, g_g1);
    cudaGetSymbolAddress((void**)&g_t2b_p, g_t2b);
    float* g_anchorT_p; cudaGetSymbolAddress((void**)&g_anchorT_p, g_anchorT);

    const int gx = (n + 127) / 128;           // 782
    const int warpBlocks = (n * 32 + 255) / 256;

    for (int i = 0; i < 2; i++) {
        gemm128<256, 1><<<dim3(gx, 1), 256>>>(X[i], enc1_w + (size_t)i * 256 * 128,
                                              enc1_b + i * 128, g_hidden_p, n, 128, 128);
        gemm128<128, 2><<<dim3(gx, 1), 256>>>(g_hidden_p, enc2_w + (size_t)i * 128 * 128,
                                              enc2_b + i * 128, Z[i], n, 128, 128);
    }
    fuse_kernel<<<warpBlocks, 256>>>(Z[0], Z[1], FZ, n);
    anchor_kernel<<<MA, 128>>>(FZ, mu_w, mu_b, zita_w, zita_b, prelu_w, ANC);
    anchorT_kernel<<<(128 * MA + 255) / 256, 256>>>(ANC);

    {
        size_t n4 = (size_t)2 * n * MA / 4;
        zero_kernel<<<(int)((n4 + 255) / 256), 256>>>((float4*)Adn[0], n4);
    }

    for (int i = 0; i < 2; i++) {
        gemm128<128, 0><<<dim3(gx, 8), 256>>>(Z[i], g_anchorT_p, nullptr, g_S_p, n, MA, MA);
        topk_kernel<<<warpBlocks, 256>>>(g_S_p, n, g_tkidx_p, g_tkw_p, Adn[i]);
        const int nn = n * KNN;
        reset_kernel<<<4, 256>>>();
        count_kernel<<<(nn + 255) / 256, 256>>>(g_tkidx_p, nn);
        scan_kernel<<<1, MA>>>();
        fill_kernel<<<(nn + 255) / 256, 256>>>(g_tkidx_p, g_tkw_p, nn);
        spmm_row128<<<warpBlocks, 256>>>(g_tkidx_p, g_tkw_p, ANC, g_hidden_p, n);
        conv_t2_128<<<MA, 128>>>(g_hidden_p, g_t2a_p);
        g1_kernel<<<MA, 32>>>(g_t2a_p, agcn1_w + (size_t)i * 128 * 32, g_g1_p);
        spmm_row32<<<warpBlocks, 256>>>(g_tkidx_p, g_tkw_p, g_g1_p, g_t1b_p, n);
        conv_t2_32<<<MA, 128>>>(g_t1b_p, g_t2b_p);
        q_kernel<<<(MA * 32 + 255) / 256, 256>>>(g_t2b_p, agcn2_w + (size_t)i * 32 * 10, Q[i]);
    }
}